// round 2
// baseline (speedup 1.0000x reference)
#include <cuda_runtime.h>
#include <math.h>

#define BB 16
#define SS 4096
#define HH 768
#define EE 8
#define CHUNKS 32
#define ROWS_PER_BLK 128   // SS/CHUNKS
#define TS 16
#define NTILES 8           // ROWS_PER_BLK/TS
#define XSTRIDE 776        // 768 + 8 pad

// smem layout in floats
#define XS_OFF   0          // [16][776]  = 12416
#define WLO_OFF  12416      // [768][4]   = 3072
#define WHI_OFF  15488      // [768][4]   = 3072
#define ASH_OFF  18560      // [8][128]   = 1024
#define EXP_OFF  19584      // [16][8]    = 128
#define RED_OFF  19712      // [8][32]    = 256
#define BIAS_OFF 19968      // [8]
#define SMEM_FLOATS 19976   // 79904 bytes

// deterministic cross-block scratch (allocation-free: device globals)
__device__ float g_num[(size_t)BB * CHUNKS * EE * HH];   // 12.6 MB
__device__ float g_den[BB * CHUNKS * EE];
__device__ float g_attn_scratch[(size_t)BB * EE * SS];   // fallback if atten not in d_out

template <int HALF>
__device__ __forceinline__ void red_round(float* v, int lane) {
    bool hi = (lane & HALF) != 0;
#pragma unroll
    for (int m = 0; m < HALF; m++) {
        float mine  = hi ? v[m + HALF] : v[m];
        float yours = hi ? v[m]        : v[m + HALF];
        v[m] = mine + __shfl_xor_sync(0xffffffffu, yours, HALF);
    }
}

__global__ __launch_bounds__(256, 2)
void fused_attn_pass1(const float* __restrict__ x,
                      const float* __restrict__ W,
                      const float* __restrict__ bias,
                      float* __restrict__ attn_out)
{
    extern __shared__ float sm[];
    float* xs      = sm + XS_OFF;
    float* wlo     = sm + WLO_OFF;
    float* whi     = sm + WHI_OFF;
    float* a_sh    = sm + ASH_OFF;
    float* exp_sh  = sm + EXP_OFF;
    float* red_sh  = sm + RED_OFF;
    float* bias_sh = sm + BIAS_OFF;

    const int t     = threadIdx.x;
    const int chunk = blockIdx.x;   // 0..31
    const int b     = blockIdx.y;   // 0..15
    const int lane  = t & 31;

    // ---- stage W (transposed to [h][e]) and bias, once per block ----
    for (int i = t; i < EE * HH; i += 256) {
        int e = i / HH, h = i % HH;
        float v = W[i];
        if (e < 4) wlo[h * 4 + e]       = v;
        else       whi[h * 4 + (e - 4)] = v;
    }
    if (t < EE) bias_sh[t] = bias[t];

    const int hg = t & 63;   // h-split group (spans warp pair)
    const int sg = t >> 6;   // s-group: 4 rows each

    float num[EE][3];
#pragma unroll
    for (int e = 0; e < EE; e++) { num[e][0] = 0.f; num[e][1] = 0.f; num[e][2] = 0.f; }
    float den_reg = 0.f;

    const float* xbase = x + ((size_t)b * SS + (size_t)chunk * ROWS_PER_BLK) * HH;

    __syncthreads();

    for (int tile = 0; tile < NTILES; tile++) {
        // ---- stage 16x768 fp32 tile into smem (coalesced float4) ----
        const float4* xin4 = (const float4*)(xbase + (size_t)tile * TS * HH);
#pragma unroll
        for (int k = 0; k < 12; k++) {
            int q = t + 256 * k;      // 0..3071 float4s
            int s = q / 192;
            int c = q % 192;
            float4 v = xin4[s * 192 + c];
            *(float4*)&xs[s * XSTRIDE + c * 4] = v;
        }
        __syncthreads();

        // ---- phase A: logits a[e][s] = W[e,:].x[s,:]  (register tile 8e x 4s) ----
        float acc[32];
#pragma unroll
        for (int m = 0; m < 32; m++) acc[m] = 0.f;

#pragma unroll
        for (int j = 0; j < 12; j++) {
            int h = hg + 64 * j;
            float4 w0 = *(const float4*)&wlo[h << 2];
            float4 w1 = *(const float4*)&whi[h << 2];
            float xv0 = xs[(4 * sg + 0) * XSTRIDE + h];
            float xv1 = xs[(4 * sg + 1) * XSTRIDE + h];
            float xv2 = xs[(4 * sg + 2) * XSTRIDE + h];
            float xv3 = xs[(4 * sg + 3) * XSTRIDE + h];
            float wv[8] = {w0.x, w0.y, w0.z, w0.w, w1.x, w1.y, w1.z, w1.w};
            float xv[4] = {xv0, xv1, xv2, xv3};
#pragma unroll
            for (int e = 0; e < 8; e++)
#pragma unroll
                for (int sl = 0; sl < 4; sl++)
                    acc[e * 4 + sl] += wv[e] * xv[sl];
        }

        // split-butterfly: after 5 rounds lane L holds total of acc index L
        red_round<16>(acc, lane);
        red_round<8>(acc, lane);
        red_round<4>(acc, lane);
        red_round<2>(acc, lane);
        red_round<1>(acc, lane);
        red_sh[t >= 256 ? 0 : t] = acc[0];   // red_sh[warp*32 + lane]
        __syncthreads();

        // ---- assemble: combine warp pairs, add bias, exp, store ----
        if (t < 128) {
            int sgf = t >> 5;         // which s-group
            int m   = t & 31;         // e*4 + sl
            int e   = m >> 2;
            int sl  = m & 3;
            float a = red_sh[(2 * sgf) * 32 + m] + red_sh[(2 * sgf + 1) * 32 + m] + bias_sh[e];
            int st = 4 * sgf + sl;    // row within tile
            a_sh[e * 128 + tile * TS + st] = a;
            exp_sh[st * 8 + e] = __expf(a);
        }
        __syncthreads();

        // ---- phase B: rank-1 accumulate num[e][h] += exp * x, + den ----
        if (t < 8) {
            float d = 0.f;
#pragma unroll
            for (int s = 0; s < TS; s++) d += exp_sh[s * 8 + t];
            den_reg += d;
        }
#pragma unroll
        for (int s = 0; s < TS; s++) {
            float4 e03 = *(const float4*)&exp_sh[s * 8];
            float4 e47 = *(const float4*)&exp_sh[s * 8 + 4];
            float xa = xs[s * XSTRIDE + t];
            float xb = xs[s * XSTRIDE + t + 256];
            float xc = xs[s * XSTRIDE + t + 512];
            num[0][0] += e03.x * xa; num[0][1] += e03.x * xb; num[0][2] += e03.x * xc;
            num[1][0] += e03.y * xa; num[1][1] += e03.y * xb; num[1][2] += e03.y * xc;
            num[2][0] += e03.z * xa; num[2][1] += e03.z * xb; num[2][2] += e03.z * xc;
            num[3][0] += e03.w * xa; num[3][1] += e03.w * xb; num[3][2] += e03.w * xc;
            num[4][0] += e47.x * xa; num[4][1] += e47.x * xb; num[4][2] += e47.x * xc;
            num[5][0] += e47.y * xa; num[5][1] += e47.y * xb; num[5][2] += e47.y * xc;
            num[6][0] += e47.z * xa; num[6][1] += e47.z * xb; num[6][2] += e47.z * xc;
            num[7][0] += e47.w * xa; num[7][1] += e47.w * xb; num[7][2] += e47.w * xc;
        }
        __syncthreads();   // protect xs/exp_sh/red_sh for next tile
    }

    // ---- epilogue: coalesced atten write + per-block partials ----
    for (int f = t; f < EE * ROWS_PER_BLK; f += 256) {
        int e = f >> 7, i = f & 127;
        attn_out[((size_t)b * EE + e) * SS + chunk * ROWS_PER_BLK + i] = a_sh[f];
    }
    int blk = b * CHUNKS + chunk;
#pragma unroll
    for (int e = 0; e < EE; e++)
#pragma unroll
        for (int k = 0; k < 3; k++)
            g_num[((size_t)blk * EE + e) * HH + t + 256 * k] = num[e][k];
    if (t < EE) g_den[blk * EE + t] = den_reg;
}

__global__ void fused_attn_pass2(float* __restrict__ out)
{
    int be = blockIdx.x;           // b*8 + e
    int b = be >> 3, e = be & 7;
    int t = threadIdx.x;

    float den = 0.f;
#pragma unroll
    for (int c = 0; c < CHUNKS; c++) den += g_den[(b * CHUNKS + c) * EE + e];
    float inv = 1.0f / den;

#pragma unroll
    for (int k = 0; k < 3; k++) {
        int h = t + 256 * k;
        float s = 0.f;
#pragma unroll 8
        for (int c = 0; c < CHUNKS; c++)
            s += g_num[((size_t)(b * CHUNKS + c) * EE + e) * HH + h];
        out[((size_t)b * EE + e) * HH + h] = s * inv;
    }
}

extern "C" void kernel_launch(void* const* d_in, const int* in_sizes, int n_in,
                              void* d_out, int out_size)
{
    const float* x    = (const float*)d_in[0];
    const float* W    = (const float*)d_in[1];
    const float* bias = (const float*)d_in[2];

    float* out_f = (float*)d_out;
    float* out_ptr;
    float* attn_ptr;

    const int OUT_N  = BB * EE * HH;          // 98304
    const int ATTN_N = BB * EE * SS;          // 524288

    if (out_size >= OUT_N + ATTN_N) {         // tuple (out, atten) concatenated
        out_ptr  = out_f;
        attn_ptr = out_f + OUT_N;
    } else if (out_size == ATTN_N) {          // only atten requested
        out_ptr  = nullptr;                   // handled below
        attn_ptr = out_f;
    } else {                                  // only out requested
        out_ptr  = out_f;
        float* dev_scratch;
        cudaGetSymbolAddress((void**)&dev_scratch, g_attn_scratch);
        attn_ptr = dev_scratch;
    }
    if (!out_ptr) {
        // still need somewhere for pass2 output; reuse head of num scratch is unsafe,
        // so point it at g_attn_scratch (never read by harness in this branch)
        float* dev_scratch;
        cudaGetSymbolAddress((void**)&dev_scratch, g_attn_scratch);
        out_ptr = dev_scratch;
    }

    size_t smem_bytes = (size_t)SMEM_FLOATS * sizeof(float);
    cudaFuncSetAttribute(fused_attn_pass1,
                         cudaFuncAttributeMaxDynamicSharedMemorySize, (int)smem_bytes);

    fused_attn_pass1<<<dim3(CHUNKS, BB), 256, smem_bytes>>>(x, W, bias, attn_ptr);
    fused_attn_pass2<<<BB * EE, 256>>>(out_ptr);
}

// round 3
// speedup vs baseline: 1.0739x; 1.0739x over previous
#include <cuda_runtime.h>
#include <math.h>

#define BB 16
#define SS 4096
#define HH 768
#define EE 8
#define CHUNKS 32
#define ROWS_PER_BLK 128   // SS/CHUNKS
#define TS 16
#define NTILES 8           // ROWS_PER_BLK/TS
#define XSTRIDE 776        // 768 + 8 pad

// smem layout in floats
#define XS_OFF   0          // [16][776]  = 12416
#define WLO_OFF  12416      // [768][4]   = 3072  (e0..e3, 16B aligned)
#define WHI_OFF  15488      // [768][4]   = 3072  (e4..e7)
#define ASH_OFF  18560      // [8][128]   = 1024
#define EXP_OFF  19584      // [8 spair][16] = 128  (layout: [sp][e*2+parity])
#define RED_OFF  19712      // [8][32]    = 256
#define BIAS_OFF 19968      // [8]
#define SMEM_FLOATS 19976   // 79904 bytes

// deterministic cross-block scratch (allocation-free: device globals)
__device__ float g_num[(size_t)BB * CHUNKS * EE * HH];   // 12.6 MB
__device__ float g_den[BB * CHUNKS * EE];
__device__ float g_attn_scratch[(size_t)BB * EE * SS];   // fallback if atten not in d_out

// ---- f32x2 packed helpers ----
typedef unsigned long long u64;

__device__ __forceinline__ u64 pack2(float lo, float hi) {
    u64 r; asm("mov.b64 %0, {%1, %2};" : "=l"(r) : "f"(lo), "f"(hi)); return r;
}
__device__ __forceinline__ void unpack2(u64 v, float& lo, float& hi) {
    asm("mov.b64 {%0, %1}, %2;" : "=f"(lo), "=f"(hi) : "l"(v));
}
__device__ __forceinline__ void ffma2(u64& d, u64 a, u64 b) {
    asm("fma.rn.f32x2 %0, %1, %2, %3;" : "=l"(d) : "l"(a), "l"(b), "l"(d));
}

template <int HALF>
__device__ __forceinline__ void red_round(float* v, int lane) {
    bool hi = (lane & HALF) != 0;
#pragma unroll
    for (int m = 0; m < HALF; m++) {
        float mine  = hi ? v[m + HALF] : v[m];
        float yours = hi ? v[m]        : v[m + HALF];
        v[m] = mine + __shfl_xor_sync(0xffffffffu, yours, HALF);
    }
}

__global__ __launch_bounds__(256, 2)
void fused_attn_pass1(const float* __restrict__ x,
                      const float* __restrict__ W,
                      const float* __restrict__ bias,
                      float* __restrict__ attn_out)
{
    extern __shared__ float sm[];
    float* xs      = sm + XS_OFF;
    float* wlo     = sm + WLO_OFF;
    float* whi     = sm + WHI_OFF;
    float* a_sh    = sm + ASH_OFF;
    float* exp_sh  = sm + EXP_OFF;
    float* red_sh  = sm + RED_OFF;
    float* bias_sh = sm + BIAS_OFF;

    const int t     = threadIdx.x;
    const int chunk = blockIdx.x;   // 0..31
    const int b     = blockIdx.y;   // 0..15
    const int lane  = t & 31;

    // ---- stage W (transposed to [h][e]) and bias, once per block ----
    for (int i = t; i < EE * HH; i += 256) {
        int e = i / HH, h = i % HH;
        float v = W[i];
        if (e < 4) wlo[h * 4 + e]       = v;
        else       whi[h * 4 + (e - 4)] = v;
    }
    if (t < EE) bias_sh[t] = bias[t];

    const int hg = t & 63;   // h-split group (spans warp pair)
    const int sg = t >> 6;   // s-group: 4 rows each

    // packed numerator accumulators: accp[e][k], lo = even s, hi = odd s
    u64 accp[EE][3];
#pragma unroll
    for (int e = 0; e < EE; e++) { accp[e][0] = 0ull; accp[e][1] = 0ull; accp[e][2] = 0ull; }
    float den_reg = 0.f;

    const float* xbase = x + ((size_t)b * SS + (size_t)chunk * ROWS_PER_BLK) * HH;

    __syncthreads();

    for (int tile = 0; tile < NTILES; tile++) {
        // ---- stage 16x768 fp32 tile into smem (coalesced float4) ----
        const float4* xin4 = (const float4*)(xbase + (size_t)tile * TS * HH);
#pragma unroll
        for (int k = 0; k < 12; k++) {
            int q = t + 256 * k;      // 0..3071 float4s
            int s = q / 192;
            int c = q % 192;
            float4 v = xin4[s * 192 + c];
            *(float4*)&xs[s * XSTRIDE + c * 4] = v;
        }
        __syncthreads();

        // ---- phase A: packed logits, acc2[epair][sl] (f32x2 over e-pairs) ----
        u64 acc2[4][4];
#pragma unroll
        for (int p = 0; p < 4; p++)
#pragma unroll
            for (int sl = 0; sl < 4; sl++) acc2[p][sl] = 0ull;

#pragma unroll
        for (int j = 0; j < 12; j++) {
            int h = hg + 64 * j;
            ulonglong2 wl = *(const ulonglong2*)&wlo[h << 2];  // (e0,e1),(e2,e3)
            ulonglong2 wh = *(const ulonglong2*)&whi[h << 2];  // (e4,e5),(e6,e7)
            u64 xp[4];
#pragma unroll
            for (int sl = 0; sl < 4; sl++) {
                float xv = xs[(4 * sg + sl) * XSTRIDE + h];
                xp[sl] = pack2(xv, xv);
            }
#pragma unroll
            for (int sl = 0; sl < 4; sl++) {
                ffma2(acc2[0][sl], wl.x, xp[sl]);
                ffma2(acc2[1][sl], wl.y, xp[sl]);
                ffma2(acc2[2][sl], wh.x, xp[sl]);
                ffma2(acc2[3][sl], wh.y, xp[sl]);
            }
        }

        // unpack into scalar layout m = e*4 + sl
        float acc[32];
#pragma unroll
        for (int p = 0; p < 4; p++)
#pragma unroll
            for (int sl = 0; sl < 4; sl++)
                unpack2(acc2[p][sl], acc[(2 * p) * 4 + sl], acc[(2 * p + 1) * 4 + sl]);

        // split-butterfly: after 5 rounds lane L holds total of acc index L
        red_round<16>(acc, lane);
        red_round<8>(acc, lane);
        red_round<4>(acc, lane);
        red_round<2>(acc, lane);
        red_round<1>(acc, lane);
        red_sh[t >= 256 ? 0 : t] = acc[0];   // red_sh[warp*32 + lane]
        __syncthreads();

        // ---- assemble: combine warp pairs, add bias, exp, store ----
        if (t < 128) {
            int sgf = t >> 5;         // which s-group
            int m   = t & 31;         // e*4 + sl
            int e   = m >> 2;
            int sl  = m & 3;
            float a = red_sh[(2 * sgf) * 32 + m] + red_sh[(2 * sgf + 1) * 32 + m] + bias_sh[e];
            int st = 4 * sgf + sl;    // row within tile
            a_sh[e * 128 + tile * TS + st] = a;
            // paired layout: [spair][e*2 + parity] so LDS.128 yields per-e (s,s+1) f32x2
            exp_sh[(st >> 1) * 16 + e * 2 + (st & 1)] = __expf(a);
        }
        __syncthreads();

        // ---- phase B: packed rank-1 accumulate over s-pairs ----
        if (t < 8) {
            float d = 0.f;
#pragma unroll
            for (int s = 0; s < TS; s++)
                d += exp_sh[(s >> 1) * 16 + t * 2 + (s & 1)];
            den_reg += d;
        }
#pragma unroll
        for (int sp = 0; sp < 8; sp++) {
            const ulonglong2* eq = (const ulonglong2*)&exp_sh[sp * 16];
            ulonglong2 q0 = eq[0];  // e0 pair, e1 pair
            ulonglong2 q1 = eq[1];  // e2, e3
            ulonglong2 q2 = eq[2];  // e4, e5
            ulonglong2 q3 = eq[3];  // e6, e7
            u64 xa = pack2(xs[(2 * sp) * XSTRIDE + t],       xs[(2 * sp + 1) * XSTRIDE + t]);
            u64 xb = pack2(xs[(2 * sp) * XSTRIDE + t + 256], xs[(2 * sp + 1) * XSTRIDE + t + 256]);
            u64 xc = pack2(xs[(2 * sp) * XSTRIDE + t + 512], xs[(2 * sp + 1) * XSTRIDE + t + 512]);
            ffma2(accp[0][0], q0.x, xa); ffma2(accp[0][1], q0.x, xb); ffma2(accp[0][2], q0.x, xc);
            ffma2(accp[1][0], q0.y, xa); ffma2(accp[1][1], q0.y, xb); ffma2(accp[1][2], q0.y, xc);
            ffma2(accp[2][0], q1.x, xa); ffma2(accp[2][1], q1.x, xb); ffma2(accp[2][2], q1.x, xc);
            ffma2(accp[3][0], q1.y, xa); ffma2(accp[3][1], q1.y, xb); ffma2(accp[3][2], q1.y, xc);
            ffma2(accp[4][0], q2.x, xa); ffma2(accp[4][1], q2.x, xb); ffma2(accp[4][2], q2.x, xc);
            ffma2(accp[5][0], q2.y, xa); ffma2(accp[5][1], q2.y, xb); ffma2(accp[5][2], q2.y, xc);
            ffma2(accp[6][0], q3.x, xa); ffma2(accp[6][1], q3.x, xb); ffma2(accp[6][2], q3.x, xc);
            ffma2(accp[7][0], q3.y, xa); ffma2(accp[7][1], q3.y, xb); ffma2(accp[7][2], q3.y, xc);
        }
        __syncthreads();   // protect xs/exp_sh/red_sh for next tile
    }

    // ---- epilogue: coalesced atten write + per-block partials ----
    for (int f = t; f < EE * ROWS_PER_BLK; f += 256) {
        int e = f >> 7, i = f & 127;
        attn_out[((size_t)b * EE + e) * SS + chunk * ROWS_PER_BLK + i] = a_sh[f];
    }
    int blk = b * CHUNKS + chunk;
#pragma unroll
    for (int e = 0; e < EE; e++)
#pragma unroll
        for (int k = 0; k < 3; k++) {
            float lo, hi;
            unpack2(accp[e][k], lo, hi);
            g_num[((size_t)blk * EE + e) * HH + t + 256 * k] = lo + hi;
        }
    if (t < EE) g_den[blk * EE + t] = den_reg;
}

__global__ __launch_bounds__(768)
void fused_attn_pass2(float* __restrict__ out)
{
    int be = blockIdx.x;           // b*8 + e
    int b = be >> 3, e = be & 7;
    int h = threadIdx.x;           // 0..767

    float den = 0.f;
#pragma unroll
    for (int c = 0; c < CHUNKS; c++) den += g_den[(b * CHUNKS + c) * EE + e];
    float inv = 1.0f / den;

    const float* base = g_num + ((size_t)(b * CHUNKS) * EE + e) * HH + h;
    float s = 0.f;
#pragma unroll
    for (int c = 0; c < CHUNKS; c++)
        s += base[(size_t)c * EE * HH];
    out[((size_t)b * EE + e) * HH + h] = s * inv;
}

extern "C" void kernel_launch(void* const* d_in, const int* in_sizes, int n_in,
                              void* d_out, int out_size)
{
    const float* x    = (const float*)d_in[0];
    const float* W    = (const float*)d_in[1];
    const float* bias = (const float*)d_in[2];

    float* out_f = (float*)d_out;
    float* out_ptr;
    float* attn_ptr;

    const int OUT_N  = BB * EE * HH;          // 98304
    const int ATTN_N = BB * EE * SS;          // 524288

    if (out_size >= OUT_N + ATTN_N) {         // tuple (out, atten) concatenated
        out_ptr  = out_f;
        attn_ptr = out_f + OUT_N;
    } else if (out_size == ATTN_N) {          // only atten requested
        out_ptr  = nullptr;
        attn_ptr = out_f;
    } else {                                  // only out requested
        out_ptr  = out_f;
        float* dev_scratch;
        cudaGetSymbolAddress((void**)&dev_scratch, g_attn_scratch);
        attn_ptr = dev_scratch;
    }
    if (!out_ptr) {
        float* dev_scratch;
        cudaGetSymbolAddress((void**)&dev_scratch, g_attn_scratch);
        out_ptr = dev_scratch;
    }

    size_t smem_bytes = (size_t)SMEM_FLOATS * sizeof(float);
    cudaFuncSetAttribute(fused_attn_pass1,
                         cudaFuncAttributeMaxDynamicSharedMemorySize, (int)smem_bytes);

    fused_attn_pass1<<<dim3(CHUNKS, BB), 256, smem_bytes>>>(x, W, bias, attn_ptr);
    fused_attn_pass2<<<BB * EE, 768>>>(out_ptr);
}